// round 15
// baseline (speedup 1.0000x reference)
#include <cuda_runtime.h>
#include <math.h>

#define Bq   4
#define Sq   2048
#define Dq   512
#define Hq   8
#define DKq  64
#define KN   9
#define NC   12     /* candidates per row */
#define BHq  32
#define Mq   8192   /* B*S */
#define EPSN 1e-12f

typedef unsigned long long ull;

// ---------------- packed fp32x2 helpers (sm_103a FFMA2) ----------------
__device__ __forceinline__ ull pack2(float x) {
    ull r;
    asm("mov.b64 %0, {%1, %1};" : "=l"(r) : "f"(x));
    return r;
}
__device__ __forceinline__ void fma2(ull& d, ull a, ull b) {
    asm("fma.rn.f32x2 %0, %1, %2, %0;" : "+l"(d) : "l"(a), "l"(b));
}
__device__ __forceinline__ float lo32(ull v) {
    return __uint_as_float((unsigned)v);
}
__device__ __forceinline__ float hi32(ull v) {
    return __uint_as_float((unsigned)(v >> 32));
}
__device__ __forceinline__ float to_tf32(float x) {
    unsigned u;
    asm("cvt.rna.tf32.f32 %0, %1;" : "=r"(u) : "f"(x));
    return __uint_as_float(u);
}

#define MMA_TF32(c, a0, a1, a2, a3, b0, b1)                                \
    asm("mma.sync.aligned.m16n8k8.row.col.f32.tf32.tf32.f32 "              \
        "{%0,%1,%2,%3}, {%4,%5,%6,%7}, {%8,%9}, {%0,%1,%2,%3};"            \
        : "+f"(c[0]), "+f"(c[1]), "+f"(c[2]), "+f"(c[3])                   \
        : "r"(a0), "r"(a1), "r"(a2), "r"(a3), "r"(b0), "r"(b1))

// ---------------- scratch (device globals; no allocation) ----------------
__device__ float g_q[BHq * Sq * DKq];      // normalized q (fp32)
__device__ float g_k[BHq * Sq * DKq];      // normalized k (fp32)
__device__ float g_v[BHq * Sq * DKq];
__device__ float g_kh[BHq * Sq * DKq];     // normalized k, tf32
__device__ float g_qh[BHq * Sq * DKq];     // normalized q, tf32
__device__ int   g_idx[BHq * Sq * KN];     // top-9 indices, sorted desc by sim
__device__ float g_y[Dq * Mq];             // y^T: [col][b*S + s']
__device__ float g_wt[KN * DKq * DKq];     // Wt[kk][c][o]
__device__ float g_xh[Mq * Dq];            // x tf32 hi; later y tf32 hi
__device__ float g_xl[Mq * Dq];            // x tf32 lo; later y tf32 lo
__device__ float g_wh[2 * Dq * Dq];        // slot0: Wv hi, slot1: Wo hi
__device__ float g_wl[2 * Dq * Dq];        // slot0: Wv lo, slot1: Wo lo

// ---------------- split kernels: hi/lo tf32 decomposition -------------------
__global__ __launch_bounds__(256) void split_x_kernel(const float* __restrict__ x)
{
    int idx = blockIdx.x * 256 + threadIdx.x;      // float4 index, 1M total
    float4 v = ((const float4*)x)[idx];
    float4 h, l;
    h.x = to_tf32(v.x); l.x = to_tf32(v.x - h.x);
    h.y = to_tf32(v.y); l.y = to_tf32(v.y - h.y);
    h.z = to_tf32(v.z); l.z = to_tf32(v.z - h.z);
    h.w = to_tf32(v.w); l.w = to_tf32(v.w - h.w);
    ((float4*)g_xh)[idx] = h;
    ((float4*)g_xl)[idx] = l;
}

__global__ __launch_bounds__(256) void split_w2_kernel(
    const float* __restrict__ Wv, const float* __restrict__ Wo)
{
    int idx = blockIdx.x * 256 + threadIdx.x;      // float4 index, 131072 total
    int z = idx >> 16;                              // 0 = Wv, 1 = Wo
    int r = idx & 65535;
    const float* W = (z == 0) ? Wv : Wo;
    float4 v = ((const float4*)W)[r];
    float4 h, l;
    h.x = to_tf32(v.x); l.x = to_tf32(v.x - h.x);
    h.y = to_tf32(v.y); l.y = to_tf32(v.y - h.y);
    h.z = to_tf32(v.z); l.z = to_tf32(v.z - h.z);
    h.w = to_tf32(v.w); l.w = to_tf32(v.w - h.w);
    ((float4*)g_wh)[idx] = h;
    ((float4*)g_wl)[idx] = l;
}

__global__ __launch_bounds__(256) void split_y_kernel()
{
    int idx = blockIdx.x * 256 + threadIdx.x;      // float4 index, 1M total
    float4 v = ((const float4*)g_y)[idx];
    float4 h, l;
    h.x = to_tf32(v.x); l.x = to_tf32(v.x - h.x);
    h.y = to_tf32(v.y); l.y = to_tf32(v.y - h.y);
    h.z = to_tf32(v.z); l.z = to_tf32(v.z - h.z);
    h.w = to_tf32(v.w); l.w = to_tf32(v.w - h.w);
    ((float4*)g_xh)[idx] = h;
    ((float4*)g_xl)[idx] = l;
}

// ---------------- Kernel A: q,k GEMM (SIMT, exact sequential-k fp32) --------
__global__ __launch_bounds__(256, 2) void qk_gemm_kernel(
    const float* __restrict__ x,
    const float* __restrict__ Wq, const float* __restrict__ bq,
    const float* __restrict__ Wk, const float* __restrict__ bk)
{
    __shared__ __align__(16) float As[16][132];
    __shared__ __align__(16) float Bs[16][132];

    const float* W; const float* bias; float* out;
    int z = blockIdx.z;
    if (z == 0) { W = Wq; bias = bq; out = g_q; }
    else        { W = Wk; bias = bk; out = g_k; }

    int m0 = blockIdx.y * 128;
    int n0 = blockIdx.x * 128;
    int tid = threadIdx.x;
    int tx = tid & 15, ty = tid >> 4;
    int r0 = ty * 8, c0 = tx * 8;

    ull acc[4][8];
#pragma unroll
    for (int i = 0; i < 4; i++)
#pragma unroll
        for (int j = 0; j < 8; j++) acc[i][j] = 0ULL;

    int lrow = tid >> 2;
    int lk   = (tid & 3) * 4;

    const float* pa0 = x + (size_t)(m0 + lrow)      * 512 + lk;
    const float* pa1 = x + (size_t)(m0 + lrow + 64) * 512 + lk;
    const float* pb0 = W + (size_t)(n0 + lrow)      * 512 + lk;
    const float* pb1 = W + (size_t)(n0 + lrow + 64) * 512 + lk;

    float4 a0 = *(const float4*)(pa0);
    float4 a1 = *(const float4*)(pa1);
    float4 b0 = *(const float4*)(pb0);
    float4 b1 = *(const float4*)(pb1);

    for (int k0 = 0; k0 < 512; k0 += 16) {
        __syncthreads();
        As[lk+0][lrow] = a0.x; As[lk+1][lrow] = a0.y; As[lk+2][lrow] = a0.z; As[lk+3][lrow] = a0.w;
        As[lk+0][lrow+64] = a1.x; As[lk+1][lrow+64] = a1.y; As[lk+2][lrow+64] = a1.z; As[lk+3][lrow+64] = a1.w;
        Bs[lk+0][lrow] = b0.x; Bs[lk+1][lrow] = b0.y; Bs[lk+2][lrow] = b0.z; Bs[lk+3][lrow] = b0.w;
        Bs[lk+0][lrow+64] = b1.x; Bs[lk+1][lrow+64] = b1.y; Bs[lk+2][lrow+64] = b1.z; Bs[lk+3][lrow+64] = b1.w;
        __syncthreads();
        if (k0 + 16 < 512) {
            a0 = *(const float4*)(pa0 + k0 + 16);
            a1 = *(const float4*)(pa1 + k0 + 16);
            b0 = *(const float4*)(pb0 + k0 + 16);
            b1 = *(const float4*)(pb1 + k0 + 16);
        }
#pragma unroll
        for (int kk = 0; kk < 16; kk++) {
            ulonglong2 ap0 = *(const ulonglong2*)&As[kk][r0];
            ulonglong2 ap1 = *(const ulonglong2*)&As[kk][r0 + 4];
            float4 bv0 = *(const float4*)&Bs[kk][c0];
            float4 bv1 = *(const float4*)&Bs[kk][c0 + 4];
            ull b2[8];
            b2[0] = pack2(bv0.x); b2[1] = pack2(bv0.y); b2[2] = pack2(bv0.z); b2[3] = pack2(bv0.w);
            b2[4] = pack2(bv1.x); b2[5] = pack2(bv1.y); b2[6] = pack2(bv1.z); b2[7] = pack2(bv1.w);
            ull a2[4] = {ap0.x, ap0.y, ap1.x, ap1.y};
#pragma unroll
            for (int i = 0; i < 4; i++)
#pragma unroll
                for (int j = 0; j < 8; j++) fma2(acc[i][j], a2[i], b2[j]);
        }
    }

    float4 bias0 = *(const float4*)(bias + n0 + c0);
    float4 bias1 = *(const float4*)(bias + n0 + c0 + 4);
    int n = n0 + c0;
    int h = n >> 6, c = n & 63;
#pragma unroll
    for (int i = 0; i < 4; i++) {
#pragma unroll
        for (int half = 0; half < 2; half++) {
            int m = m0 + r0 + 2 * i + half;
            int bb = m >> 11;
            int s  = m & 2047;
            float4 o0, o1;
            if (half == 0) {
                o0.x = lo32(acc[i][0]) + bias0.x; o0.y = lo32(acc[i][1]) + bias0.y;
                o0.z = lo32(acc[i][2]) + bias0.z; o0.w = lo32(acc[i][3]) + bias0.w;
                o1.x = lo32(acc[i][4]) + bias1.x; o1.y = lo32(acc[i][5]) + bias1.y;
                o1.z = lo32(acc[i][6]) + bias1.z; o1.w = lo32(acc[i][7]) + bias1.w;
            } else {
                o0.x = hi32(acc[i][0]) + bias0.x; o0.y = hi32(acc[i][1]) + bias0.y;
                o0.z = hi32(acc[i][2]) + bias0.z; o0.w = hi32(acc[i][3]) + bias0.w;
                o1.x = hi32(acc[i][4]) + bias1.x; o1.y = hi32(acc[i][5]) + bias1.y;
                o1.z = hi32(acc[i][6]) + bias1.z; o1.w = hi32(acc[i][7]) + bias1.w;
            }
            float* po = out + ((size_t)(bb * Hq + h) * Sq + s) * DKq + c;
            *(float4*)po = o0;
            *(float4*)(po + 4) = o1;
        }
    }
}

// ---------------- Kernel A2: v GEMM via 3xTF32 MMA, 128x64 tiles, 3 blk/SM --
__global__ __launch_bounds__(256, 3) void v_mma_kernel(const float* __restrict__ bv)
{
    __shared__ __align__(16) float Ahs[128 * 20];
    __shared__ __align__(16) float Als[128 * 20];
    __shared__ __align__(16) float Bhs[64 * 20];
    __shared__ __align__(16) float Bls[64 * 20];

    int m0 = blockIdx.y * 128;
    int n0 = blockIdx.x * 64;
    int tid = threadIdx.x;
    int lane = tid & 31, wid = tid >> 5;
    int g = lane >> 2, t4 = lane & 3;
    int wy = wid & 3, wx = wid >> 2;

    float c[2][4][4];
#pragma unroll
    for (int mi = 0; mi < 2; mi++)
#pragma unroll
        for (int ni = 0; ni < 4; ni++)
#pragma unroll
            for (int u = 0; u < 4; u++) c[mi][ni][u] = 0.0f;

    int lrow = tid >> 2, lkq = (tid & 3) * 4;
    const float* pxh0 = g_xh + (size_t)(m0 + lrow)      * 512 + lkq;
    const float* pxh1 = g_xh + (size_t)(m0 + lrow + 64) * 512 + lkq;
    const float* pxl0 = g_xl + (size_t)(m0 + lrow)      * 512 + lkq;
    const float* pxl1 = g_xl + (size_t)(m0 + lrow + 64) * 512 + lkq;
    const float* pwh  = g_wh + (size_t)(n0 + lrow) * 512 + lkq;   // slot0 Wv
    const float* pwl  = g_wl + (size_t)(n0 + lrow) * 512 + lkq;

    for (int k0 = 0; k0 < 512; k0 += 16) {
        __syncthreads();
        *(float4*)&Ahs[lrow * 20 + lkq]        = *(const float4*)(pxh0 + k0);
        *(float4*)&Ahs[(lrow + 64) * 20 + lkq] = *(const float4*)(pxh1 + k0);
        *(float4*)&Als[lrow * 20 + lkq]        = *(const float4*)(pxl0 + k0);
        *(float4*)&Als[(lrow + 64) * 20 + lkq] = *(const float4*)(pxl1 + k0);
        *(float4*)&Bhs[lrow * 20 + lkq]        = *(const float4*)(pwh + k0);
        *(float4*)&Bls[lrow * 20 + lkq]        = *(const float4*)(pwl + k0);
        __syncthreads();
#pragma unroll
        for (int kc = 0; kc < 2; kc++) {
            float afh[2][4], afl[2][4];
#pragma unroll
            for (int mi = 0; mi < 2; mi++) {
                int ao = (wy * 32 + mi * 16 + g) * 20 + kc * 8 + t4;
                afh[mi][0] = Ahs[ao];       afh[mi][1] = Ahs[ao + 160];
                afh[mi][2] = Ahs[ao + 4];   afh[mi][3] = Ahs[ao + 164];
                afl[mi][0] = Als[ao];       afl[mi][1] = Als[ao + 160];
                afl[mi][2] = Als[ao + 4];   afl[mi][3] = Als[ao + 164];
            }
#pragma unroll
            for (int ni = 0; ni < 4; ni++) {
                int bo = (wx * 32 + ni * 8 + g) * 20 + kc * 8 + t4;
                unsigned bh0 = __float_as_uint(Bhs[bo]);
                unsigned bh1 = __float_as_uint(Bhs[bo + 4]);
                unsigned bl0 = __float_as_uint(Bls[bo]);
                unsigned bl1 = __float_as_uint(Bls[bo + 4]);
#pragma unroll
                for (int mi = 0; mi < 2; mi++) {
                    unsigned a0 = __float_as_uint(afh[mi][0]);
                    unsigned a1 = __float_as_uint(afh[mi][1]);
                    unsigned a2 = __float_as_uint(afh[mi][2]);
                    unsigned a3 = __float_as_uint(afh[mi][3]);
                    unsigned l0 = __float_as_uint(afl[mi][0]);
                    unsigned l1 = __float_as_uint(afl[mi][1]);
                    unsigned l2 = __float_as_uint(afl[mi][2]);
                    unsigned l3 = __float_as_uint(afl[mi][3]);
                    MMA_TF32(c[mi][ni], l0, l1, l2, l3, bh0, bh1);  // lo*hi
                    MMA_TF32(c[mi][ni], a0, a1, a2, a3, bl0, bl1);  // hi*lo
                    MMA_TF32(c[mi][ni], a0, a1, a2, a3, bh0, bh1);  // hi*hi
                }
            }
        }
    }

#pragma unroll
    for (int ni = 0; ni < 4; ni++) {
        int n = n0 + wx * 32 + ni * 8 + 2 * t4;
        float2 bi = *(const float2*)(bv + n);
        int h = n >> 6, ci = n & 63;
#pragma unroll
        for (int mi = 0; mi < 2; mi++) {
#pragma unroll
            for (int half = 0; half < 2; half++) {
                int m = m0 + wy * 32 + mi * 16 + g + half * 8;
                int bb = m >> 11, s = m & 2047;
                float2 o;
                o.x = c[mi][ni][half * 2 + 0] + bi.x;
                o.y = c[mi][ni][half * 2 + 1] + bi.y;
                *(float2*)(g_v + ((size_t)(bb * Hq + h) * Sq + s) * DKq + ci) = o;
            }
        }
    }
}

// ---------------- Kernel B: L2-normalize q,k (in place) + tf32 copy ---------
__global__ __launch_bounds__(256) void normalize_split_kernel()
{
    int gw   = blockIdx.x * 8 + (threadIdx.x >> 5);
    int lane = threadIdx.x & 31;
    float* p; float* ph;
    if (gw < BHq * Sq) {
        p  = g_k  + (size_t)gw * 64;
        ph = g_kh + (size_t)gw * 64;
    } else {
        int r = gw - BHq * Sq;
        p  = g_q  + (size_t)r * 64;
        ph = g_qh + (size_t)r * 64;
    }
    float v0 = p[lane], v1 = p[lane + 32];
    float ss = v0 * v0 + v1 * v1;
#pragma unroll
    for (int o = 16; o; o >>= 1) ss += __shfl_xor_sync(0xffffffffu, ss, o);
    float inv = 1.0f / fmaxf(sqrtf(ss), EPSN);
    float x0 = v0 * inv, x1 = v1 * inv;
    p[lane]       = x0;
    p[lane + 32]  = x1;
    ph[lane]      = to_tf32(x0);
    ph[lane + 32] = to_tf32(x1);
}

// ---------------- Kernel C: tf32 mma pruning (top-12) + exact fp32 rescore --
__global__ __launch_bounds__(256, 3) void sim_topk_kernel()
{
    extern __shared__ __align__(16) float sm[];
    float* As = sm;            // [64][68] kn tf32
    float* Bs = sm + 4352;     // [64][68] qn tf32
    float* Ss = sm + 8704;     // [64][68] sim tile; later kn fp32 tile

    int bh = blockIdx.y;
    int i0 = blockIdx.x * 64;
    int tid = threadIdx.x;
    int lane = tid & 31;
    int wid = tid >> 5;
    int g = lane >> 2, t4 = lane & 3;
    int wr = (wid & 3) * 16;
    int jbase = (wid >> 2) * 32;

    const float* khb = g_kh + (size_t)bh * Sq * DKq;
    const float* qhb = g_qh + (size_t)bh * Sq * DKq;

#pragma unroll
    for (int p = 0; p < 4; p++) {
        int f = tid + 256 * p;
        int r = f >> 4, dq = (f & 15) * 4;
        *(float4*)&As[r * 68 + dq] = *(const float4*)(khb + (size_t)(i0 + r) * 64 + dq);
    }

    float tv[NC]; int ti[NC];
#pragma unroll
    for (int q = 0; q < NC; q++) { tv[q] = -1.0f; ti[q] = 0; }

    int row = tid >> 2, part = tid & 3;

    const unsigned* Ah = (const unsigned*)As;
    const unsigned* Bh = (const unsigned*)Bs;

    for (int j0 = 0; j0 < Sq; j0 += 64) {
        __syncthreads();
#pragma unroll
        for (int p = 0; p < 4; p++) {
            int f = tid + 256 * p;
            int r = f >> 4, dq = (f & 15) * 4;
            *(float4*)&Bs[r * 68 + dq] =
                *(const float4*)(qhb + (size_t)(j0 + r) * 64 + dq);
        }
        __syncthreads();

        float c[4][4];
#pragma unroll
        for (int jc = 0; jc < 4; jc++)
#pragma unroll
            for (int u = 0; u < 4; u++) c[jc][u] = 0.0f;

#pragma unroll
        for (int kc = 0; kc < 8; kc++) {
            int ao = (wr + g) * 68 + kc * 8 + t4;
            unsigned ah0 = Ah[ao], ah1 = Ah[ao + 544], ah2 = Ah[ao + 4], ah3 = Ah[ao + 548];
#pragma unroll
            for (int jc = 0; jc < 4; jc++) {
                int bo = (jbase + jc * 8 + g) * 68 + kc * 8 + t4;
                unsigned bh0 = Bh[bo], bh1 = Bh[bo + 4];
                MMA_TF32(c[jc], ah0, ah1, ah2, ah3, bh0, bh1);
            }
        }

#pragma unroll
        for (int jc = 0; jc < 4; jc++) {
            int col = jbase + jc * 8 + 2 * t4;
            int rr  = wr + g;
            float2 s0, s1;
            s0.x = fmaxf(c[jc][0], 0.0f); s0.y = fmaxf(c[jc][1], 0.0f);
            s1.x = fmaxf(c[jc][2], 0.0f); s1.y = fmaxf(c[jc][3], 0.0f);
            *(float2*)&Ss[rr * 68 + col]       = s0;
            *(float2*)&Ss[(rr + 8) * 68 + col] = s1;
        }
        __syncthreads();

#pragma unroll
        for (int t = 0; t < 4; t++) {
            float4 v4 = *(const float4*)&Ss[row * 68 + part * 16 + t * 4];
            int cb = j0 + part * 16 + t * 4;
            float vv[4] = {v4.x, v4.y, v4.z, v4.w};
#pragma unroll
            for (int u = 0; u < 4; u++) {
                float v = vv[u];
                if (v > tv[NC - 1]) {
                    tv[NC - 1] = v; ti[NC - 1] = cb + u;
#pragma unroll
                    for (int q = NC - 1; q > 0; q--) {
                        if (tv[q] > tv[q - 1]) {
                            float tf = tv[q]; tv[q] = tv[q - 1]; tv[q - 1] = tf;
                            int tt = ti[q]; ti[q] = ti[q - 1]; ti[q - 1] = tt;
                        }
                    }
                }
            }
        }
    }
    __syncthreads();

    float* Mv = sm;
    int*   Mi = (int*)(sm + 3072);
    int*   Ci = (int*)(sm + 6144);
    float* Cv = sm + 6912;
#pragma unroll
    for (int q = 0; q < NC; q++) {
        Mv[tid * NC + q] = tv[q];
        Mi[tid * NC + q] = ti[q];
    }
#pragma unroll
    for (int p = 0; p < 4; p++) {
        int f = tid + 256 * p;
        int r = f >> 4, dq = (f & 15) * 4;
        *(float4*)&Ss[r * 68 + dq] =
            *(const float4*)(g_k + ((size_t)bh * Sq + i0 + r) * 64 + dq);
    }
    __syncthreads();

    if (tid < 64) {
        int pos0 = 0, pos1 = 0, pos2 = 0, pos3 = 0;
        for (int kk = 0; kk < NC; kk++) {
            float bv = -2.0f; int bi = 0x7fffffff, bp = 0;
            {
                float v = Mv[(tid * 4 + 0) * NC + pos0]; int ix = Mi[(tid * 4 + 0) * NC + pos0];
                if (v > bv || (v == bv && ix < bi)) { bv = v; bi = ix; bp = 0; }
            }
            {
                float v = Mv[(tid * 4 + 1) * NC + pos1]; int ix = Mi[(tid * 4 + 1) * NC + pos1];
                if (v > bv || (v == bv && ix < bi)) { bv = v; bi = ix; bp = 1; }
            }
            {
                float v = Mv[(tid * 4 + 2) * NC + pos2]; int ix = Mi[(tid * 4 + 2) * NC + pos2];
                if (v > bv || (v == bv && ix < bi)) { bv = v; bi = ix; bp = 2; }
            }
            {
                float v = Mv[(tid * 4 + 3) * NC + pos3]; int ix = Mi[(tid * 4 + 3) * NC + pos3];
                if (v > bv || (v == bv && ix < bi)) { bv = v; bi = ix; bp = 3; }
            }
            Ci[tid * NC + kk] = bi;
            if (bp == 0) pos0++; else if (bp == 1) pos1++; else if (bp == 2) pos2++; else pos3++;
        }
    }
    __syncthreads();

    {
        int r = tid >> 2, p = tid & 3;
        const float* kr = &Ss[r * 68];
#pragma unroll
        for (int s2 = 0; s2 < 3; s2++) {
            int c2 = p + 4 * s2;
            int j = Ci[r * NC + c2];
            const float* qrow = g_q + ((size_t)bh * Sq + j) * 64;
            float s = 0.0f;
#pragma unroll
            for (int d = 0; d < 64; d += 4) {
                float4 qv = *(const float4*)(qrow + d);
                s = fmaf(kr[d + 0], qv.x, s);
                s = fmaf(kr[d + 1], qv.y, s);
                s = fmaf(kr[d + 2], qv.z, s);
                s = fmaf(kr[d + 3], qv.w, s);
            }
            Cv[r * NC + c2] = fmaxf(s, 0.0f);
        }
    }
    __syncthreads();

    if (tid < 64) {
        float vals[NC]; int cand[NC];
#pragma unroll
        for (int c2 = 0; c2 < NC; c2++) {
            vals[c2] = Cv[tid * NC + c2];
            cand[c2] = Ci[tid * NC + c2];
        }
        int obase = (bh * Sq + i0 + tid) * KN;
        for (int a = 0; a < KN; a++) {
            int best = a;
            for (int c2 = a + 1; c2 < NC; c2++) {
                if (vals[c2] > vals[best] ||
                    (vals[c2] == vals[best] && cand[c2] < cand[best]))
                    best = c2;
            }
            float tvv = vals[a]; vals[a] = vals[best]; vals[best] = tvv;
            int   tii = cand[a]; cand[a] = cand[best]; cand[best] = tii;
            g_idx[obase + a] = cand[a];
        }
    }
}

// ---------------- prep: transpose conv_w [o][c][kk] -> Wt[kk][c][o] ---------
__global__ void transpose_convw_kernel(const float* __restrict__ w)
{
    int t = blockIdx.x * 256 + threadIdx.x;
    if (t < KN * DKq * DKq) {
        int o = t & 63, c = (t >> 6) & 63, kk = t >> 12;
        g_wt[t] = w[(o * 64 + c) * KN + kk];
    }
}

// ---------------- Kernel D: gather v by idx + grouped conv (R9, 128 thr) ----
__global__ __launch_bounds__(128, 2) void conv_kernel(const float* __restrict__ convb)
{
    extern __shared__ float smd[];
    float* v_s  = smd;                   // [288][64]
    float* w_s  = smd + 288 * 64;        // [64 c][64 o]
    int*   sidx = (int*)(smd + 288 * 64 + 4096);  // [288]

    int bh = blockIdx.y;
    int i0 = blockIdx.x * 32;
    int b  = bh >> 3, h = bh & 7;
    int tid = threadIdx.x;

    for (int t = tid; t < 288; t += 128)
        sidx[t] = g_idx[(bh * Sq + i0 + t / KN) * KN + (t % KN)];

    float4 wreg[8];
#pragma unroll
    for (int p = 0; p < 8; p++)
        wreg[p] = *(const float4*)(g_wt + (tid + 128 * p) * 4);

    __syncthreads();

    const float* vbase = g_v + (size_t)bh * Sq * DKq;
    for (int p = 0; p < 36; p++) {
        int f = tid + 128 * p;
        int r = f >> 4, fq = (f & 15) * 4;
        int j = sidx[r];
        float4 vv = *(const float4*)(vbase + (size_t)j * 64 + fq);
        *(float4*)&v_s[r * 64 + fq] = vv;
    }

    int og = tid & 15; int o0 = og * 4;
    int ig = tid >> 4;
    ull acc[4][2];
#pragma unroll
    for (int t = 0; t < 4; t++) { acc[t][0] = 0ULL; acc[t][1] = 0ULL; }

    for (int kk = 0; kk < KN; kk++) {
        __syncthreads();
#pragma unroll
        for (int p = 0; p < 8; p++)
            *(float4*)&w_s[(tid + 128 * p) * 4] = wreg[p];
        __syncthreads();
        if (kk + 1 < KN) {
#pragma unroll
            for (int p = 0; p < 8; p++)
                wreg[p] = *(const float4*)(g_wt + (kk + 1) * 4096 + (tid + 128 * p) * 4);
        }
#pragma unroll 4
        for (int c = 0; c < 64; c++) {
            ulonglong2 wp = *(const ulonglong2*)&w_s[c * 64 + o0];
#pragma unroll
            for (int t = 0; t < 4; t++) {
                ull v2 = pack2(v_s[(((ig * 4 + t) * KN) + kk) * 64 + c]);
                fma2(acc[t][0], v2, wp.x);
                fma2(acc[t][1], v2, wp.y);
            }
        }
    }

    float4 cb = *(const float4*)(convb + o0);
    int colbase = (h * 64 + (i0 >> 5)) * Mq + b * Sq;
#pragma unroll
    for (int t = 0; t < 4; t++) {
        int il = ig * 4 + t;
        int sp = ((i0 + il) & 31) * 64 + o0;
        float4 o;
        o.x = lo32(acc[t][0]) + cb.x;
        o.y = hi32(acc[t][0]) + cb.y;
        o.z = lo32(acc[t][1]) + cb.z;
        o.w = hi32(acc[t][1]) + cb.w;
        *(float4*)&g_y[colbase + sp] = o;
    }
}

// ---------------- Kernel E: out GEMM via 3xTF32 MMA, 128x64 tiles, 3 blk/SM -
__global__ __launch_bounds__(256, 3) void out_mma_kernel(
    const float* __restrict__ bo, float* __restrict__ outp)
{
    __shared__ __align__(16) float Ahs[16 * 132];
    __shared__ __align__(16) float Als[16 * 132];
    __shared__ __align__(16) float Bhs[64 * 20];
    __shared__ __align__(16) float Bls[64 * 20];

    int m0 = blockIdx.y * 128, n0 = blockIdx.x * 64;
    int tid = threadIdx.x;
    int lane = tid & 31, wid = tid >> 5;
    int g = lane >> 2, t4 = lane & 3;
    int wy = wid & 3, wx = wid >> 2;

    float c[2][4][4];
#pragma unroll
    for (int mi = 0; mi < 2; mi++)
#pragma unroll
        for (int ni = 0; ni < 4; ni++)
#pragma unroll
            for (int u = 0; u < 4; u++) c[mi][ni][u] = 0.0f;

    int fk = tid >> 5, fm = tid & 31;            // A fill: rows fk, fk+8
    int lrow = tid >> 2, lkq = (tid & 3) * 4;    // B fill: one row per thread

    const float* pah0 = g_xh + (size_t)fk * Mq + m0 + fm * 4;        // y hi
    const float* pah1 = g_xh + (size_t)(fk + 8) * Mq + m0 + fm * 4;
    const float* pal0 = g_xl + (size_t)fk * Mq + m0 + fm * 4;        // y lo
    const float* pal1 = g_xl + (size_t)(fk + 8) * Mq + m0 + fm * 4;
    const float* pbh  = g_wh + 262144 + (size_t)(n0 + lrow) * 512 + lkq;  // Wo hi
    const float* pbl  = g_wl + 262144 + (size_t)(n0 + lrow) * 512 + lkq;  // Wo lo

    for (int k0 = 0; k0 < 512; k0 += 16) {
        __syncthreads();
        *(float4*)&Ahs[fk * 132 + fm * 4]       = *(const float4*)(pah0 + (size_t)k0 * Mq);
        *(float4*)&Ahs[(fk + 8) * 132 + fm * 4] = *(const float4*)(pah1 + (size_t)k0 * Mq);
        *(float4*)&Als[fk * 132 + fm * 4]       = *(const float4*)(pal0 + (size_t)k0 * Mq);
        *(float4*)&Als[(fk + 8) * 132 + fm * 4] = *(const float4*)(pal1 + (size_t)k0 * Mq);
        *(float4*)&Bhs[lrow * 20 + lkq]         = *(const float4*)(pbh + k0);
        *(float4*)&Bls[lrow * 20 + lkq]         = *(const float4*)(pbl + k0);
        __syncthreads();
#pragma unroll
        for (int kc = 0; kc < 2; kc++) {
            float afh[2][4], afl[2][4];
#pragma unroll
            for (int mi = 0; mi < 2; mi++) {
                int mloc = wy * 32 + mi * 16 + g;
                int ao = (kc * 8 + t4) * 132 + mloc;
                afh[mi][0] = Ahs[ao];             afh[mi][1] = Ahs[ao + 8];
                afh[mi][2] = Ahs[ao + 4 * 132];   afh[mi][3] = Ahs[ao + 4 * 132 + 8];
                afl[mi][0] = Als[ao];             afl[mi][1] = Als[ao + 8];
                afl[mi][2] = Als[ao + 4 * 132];   afl[mi][3] = Als[ao + 4 * 132 + 8];
            }
#pragma unroll
            for (int ni = 0; ni < 4; ni++) {
                int bo_ = (wx * 32 + ni * 8 + g) * 20 + kc * 8 + t4;
                unsigned bh0 = __float_as_uint(Bhs[bo_]);
                unsigned bh1 = __float_as_uint(Bhs[bo_ + 4]);
                unsigned bl0 = __float_as_uint(Bls[bo_]);
                unsigned bl1 = __float_as_uint(Bls[bo_ + 4]);
#pragma unroll
                for (int mi = 0; mi < 2; mi++) {
                    unsigned a0 = __float_as_uint(afh[mi][0]);
                    unsigned a1 = __float_as_uint(afh[mi][1]);
                    unsigned a2 = __float_as_uint(afh[mi][2]);
                    unsigned a3 = __float_as_uint(afh[mi][3]);
                    unsigned l0 = __float_as_uint(afl[mi][0]);
                    unsigned l1 = __float_as_uint(afl[mi][1]);
                    unsigned l2 = __float_as_uint(afl[mi][2]);
                    unsigned l3 = __float_as_uint(afl[mi][3]);
                    MMA_TF32(c[mi][ni], l0, l1, l2, l3, bh0, bh1);  // lo*hi
                    MMA_TF32(c[mi][ni], a0, a1, a2, a3, bl0, bl1);  // hi*lo
                    MMA_TF32(c[mi][ni], a0, a1, a2, a3, bh0, bh1);  // hi*hi
                }
            }
        }
    }

#pragma unroll
    for (int ni = 0; ni < 4; ni++) {
        int n = n0 + wx * 32 + ni * 8 + 2 * t4;
        float2 bi = *(const float2*)(bo + n);
#pragma unroll
        for (int mi = 0; mi < 2; mi++) {
#pragma unroll
            for (int half = 0; half < 2; half++) {
                int m = m0 + wy * 32 + mi * 16 + g + half * 8;
                float2 o;
                o.x = c[mi][ni][half * 2 + 0] + bi.x;
                o.y = c[mi][ni][half * 2 + 1] + bi.y;
                *(float2*)(outp + (size_t)m * 512 + n) = o;
            }
        }
    }
}

// ---------------- launch -----------------------------------------------------
extern "C" void kernel_launch(void* const* d_in, const int* in_sizes, int n_in,
                              void* d_out, int out_size)
{
    (void)in_sizes; (void)n_in; (void)out_size;
    const float* x      = (const float*)d_in[0];
    const float* Wq_w   = (const float*)d_in[1];
    const float* Wq_b   = (const float*)d_in[2];
    const float* Wk_w   = (const float*)d_in[3];
    const float* Wk_b   = (const float*)d_in[4];
    const float* Wv_w   = (const float*)d_in[5];
    const float* Wv_b   = (const float*)d_in[6];
    const float* Wo_w   = (const float*)d_in[7];
    const float* Wo_b   = (const float*)d_in[8];
    const float* conv_w = (const float*)d_in[9];
    const float* conv_b = (const float*)d_in[10];
    float* outp = (float*)d_out;

    const int SMEM_C = 13056 * 4;                            // 52224 B
    const int SMEM_D = (288 * 64 + 64 * 64) * 4 + 288 * 4;   // 91264 B
    cudaFuncSetAttribute(sim_topk_kernel, cudaFuncAttributeMaxDynamicSharedMemorySize, SMEM_C);
    cudaFuncSetAttribute(conv_kernel,     cudaFuncAttributeMaxDynamicSharedMemorySize, SMEM_D);

    split_x_kernel<<<4096, 256>>>(x);                     // 1M float4
    split_w2_kernel<<<512, 256>>>(Wv_w, Wo_w);            // 131072 float4
    qk_gemm_kernel<<<dim3(4, 64, 2), 256>>>(x, Wq_w, Wq_b, Wk_w, Wk_b);
    v_mma_kernel<<<dim3(8, 64), 256>>>(Wv_b);
    normalize_split_kernel<<<16384, 256>>>();
    transpose_convw_kernel<<<144, 256>>>(conv_w);
    sim_topk_kernel<<<dim3(32, 32), 256, SMEM_C>>>();
    conv_kernel<<<dim3(64, 32), 128, SMEM_D>>>(conv_b);
    split_y_kernel<<<4096, 256>>>();
    out_mma_kernel<<<dim3(8, 64), 256>>>(Wo_b, outp);
}

// round 16
// speedup vs baseline: 1.0648x; 1.0648x over previous
#include <cuda_runtime.h>
#include <math.h>

#define Bq   4
#define Sq   2048
#define Dq   512
#define Hq   8
#define DKq  64
#define KN   9
#define NC   12     /* candidates per row */
#define BHq  32
#define Mq   8192   /* B*S */
#define EPSN 1e-12f

typedef unsigned long long ull;

// ---------------- packed fp32x2 helpers (sm_103a FFMA2) ----------------
__device__ __forceinline__ ull pack2(float x) {
    ull r;
    asm("mov.b64 %0, {%1, %1};" : "=l"(r) : "f"(x));
    return r;
}
__device__ __forceinline__ void fma2(ull& d, ull a, ull b) {
    asm("fma.rn.f32x2 %0, %1, %2, %0;" : "+l"(d) : "l"(a), "l"(b));
}
__device__ __forceinline__ float lo32(ull v) {
    return __uint_as_float((unsigned)v);
}
__device__ __forceinline__ float hi32(ull v) {
    return __uint_as_float((unsigned)(v >> 32));
}
__device__ __forceinline__ float to_tf32(float x) {
    unsigned u;
    asm("cvt.rna.tf32.f32 %0, %1;" : "=r"(u) : "f"(x));
    return __uint_as_float(u);
}

#define MMA_TF32(c, a0, a1, a2, a3, b0, b1)                                \
    asm("mma.sync.aligned.m16n8k8.row.col.f32.tf32.tf32.f32 "              \
        "{%0,%1,%2,%3}, {%4,%5,%6,%7}, {%8,%9}, {%0,%1,%2,%3};"            \
        : "+f"(c[0]), "+f"(c[1]), "+f"(c[2]), "+f"(c[3])                   \
        : "r"(a0), "r"(a1), "r"(a2), "r"(a3), "r"(b0), "r"(b1))

// ---------------- scratch (device globals; no allocation) ----------------
__device__ float g_q[BHq * Sq * DKq];      // normalized q (fp32)
__device__ float g_k[BHq * Sq * DKq];      // normalized k (fp32)
__device__ float g_v[BHq * Sq * DKq];
__device__ float g_kh[BHq * Sq * DKq];     // normalized k, tf32
__device__ float g_qh[BHq * Sq * DKq];     // normalized q, tf32
__device__ int   g_idx[BHq * Sq * KN];     // top-9 indices, sorted desc by sim
__device__ float g_wt[KN * DKq * DKq];     // Wt[kk][c][o]
__device__ float g_xh[Mq * Dq];            // x tf32 hi; later y^T tf32 hi
__device__ float g_xl[Mq * Dq];            // x tf32 lo; later y^T tf32 lo
__device__ float g_wh[2 * Dq * Dq];        // slot0: Wv hi, slot1: Wo hi
__device__ float g_wl[2 * Dq * Dq];        // slot0: Wv lo, slot1: Wo lo

// ---------------- split kernels: hi/lo tf32 decomposition -------------------
__global__ __launch_bounds__(256) void split_x_kernel(const float* __restrict__ x)
{
    int idx = blockIdx.x * 256 + threadIdx.x;      // float4 index, 1M total
    float4 v = ((const float4*)x)[idx];
    float4 h, l;
    h.x = to_tf32(v.x); l.x = to_tf32(v.x - h.x);
    h.y = to_tf32(v.y); l.y = to_tf32(v.y - h.y);
    h.z = to_tf32(v.z); l.z = to_tf32(v.z - h.z);
    h.w = to_tf32(v.w); l.w = to_tf32(v.w - h.w);
    ((float4*)g_xh)[idx] = h;
    ((float4*)g_xl)[idx] = l;
}

__global__ __launch_bounds__(256) void split_w2_kernel(
    const float* __restrict__ Wv, const float* __restrict__ Wo)
{
    int idx = blockIdx.x * 256 + threadIdx.x;      // float4 index, 131072 total
    int z = idx >> 16;                              // 0 = Wv, 1 = Wo
    int r = idx & 65535;
    const float* W = (z == 0) ? Wv : Wo;
    float4 v = ((const float4*)W)[r];
    float4 h, l;
    h.x = to_tf32(v.x); l.x = to_tf32(v.x - h.x);
    h.y = to_tf32(v.y); l.y = to_tf32(v.y - h.y);
    h.z = to_tf32(v.z); l.z = to_tf32(v.z - h.z);
    h.w = to_tf32(v.w); l.w = to_tf32(v.w - h.w);
    ((float4*)g_wh)[idx] = h;
    ((float4*)g_wl)[idx] = l;
}

// ---------------- Kernel A: q,k GEMM (SIMT, exact sequential-k fp32) --------
__global__ __launch_bounds__(256, 2) void qk_gemm_kernel(
    const float* __restrict__ x,
    const float* __restrict__ Wq, const float* __restrict__ bq,
    const float* __restrict__ Wk, const float* __restrict__ bk)
{
    __shared__ __align__(16) float As[16][132];
    __shared__ __align__(16) float Bs[16][132];

    const float* W; const float* bias; float* out;
    int z = blockIdx.z;
    if (z == 0) { W = Wq; bias = bq; out = g_q; }
    else        { W = Wk; bias = bk; out = g_k; }

    int m0 = blockIdx.y * 128;
    int n0 = blockIdx.x * 128;
    int tid = threadIdx.x;
    int tx = tid & 15, ty = tid >> 4;
    int r0 = ty * 8, c0 = tx * 8;

    ull acc[4][8];
#pragma unroll
    for (int i = 0; i < 4; i++)
#pragma unroll
        for (int j = 0; j < 8; j++) acc[i][j] = 0ULL;

    int lrow = tid >> 2;
    int lk   = (tid & 3) * 4;

    const float* pa0 = x + (size_t)(m0 + lrow)      * 512 + lk;
    const float* pa1 = x + (size_t)(m0 + lrow + 64) * 512 + lk;
    const float* pb0 = W + (size_t)(n0 + lrow)      * 512 + lk;
    const float* pb1 = W + (size_t)(n0 + lrow + 64) * 512 + lk;

    float4 a0 = *(const float4*)(pa0);
    float4 a1 = *(const float4*)(pa1);
    float4 b0 = *(const float4*)(pb0);
    float4 b1 = *(const float4*)(pb1);

    for (int k0 = 0; k0 < 512; k0 += 16) {
        __syncthreads();
        As[lk+0][lrow] = a0.x; As[lk+1][lrow] = a0.y; As[lk+2][lrow] = a0.z; As[lk+3][lrow] = a0.w;
        As[lk+0][lrow+64] = a1.x; As[lk+1][lrow+64] = a1.y; As[lk+2][lrow+64] = a1.z; As[lk+3][lrow+64] = a1.w;
        Bs[lk+0][lrow] = b0.x; Bs[lk+1][lrow] = b0.y; Bs[lk+2][lrow] = b0.z; Bs[lk+3][lrow] = b0.w;
        Bs[lk+0][lrow+64] = b1.x; Bs[lk+1][lrow+64] = b1.y; Bs[lk+2][lrow+64] = b1.z; Bs[lk+3][lrow+64] = b1.w;
        __syncthreads();
        if (k0 + 16 < 512) {
            a0 = *(const float4*)(pa0 + k0 + 16);
            a1 = *(const float4*)(pa1 + k0 + 16);
            b0 = *(const float4*)(pb0 + k0 + 16);
            b1 = *(const float4*)(pb1 + k0 + 16);
        }
#pragma unroll
        for (int kk = 0; kk < 16; kk++) {
            ulonglong2 ap0 = *(const ulonglong2*)&As[kk][r0];
            ulonglong2 ap1 = *(const ulonglong2*)&As[kk][r0 + 4];
            float4 bv0 = *(const float4*)&Bs[kk][c0];
            float4 bv1 = *(const float4*)&Bs[kk][c0 + 4];
            ull b2[8];
            b2[0] = pack2(bv0.x); b2[1] = pack2(bv0.y); b2[2] = pack2(bv0.z); b2[3] = pack2(bv0.w);
            b2[4] = pack2(bv1.x); b2[5] = pack2(bv1.y); b2[6] = pack2(bv1.z); b2[7] = pack2(bv1.w);
            ull a2[4] = {ap0.x, ap0.y, ap1.x, ap1.y};
#pragma unroll
            for (int i = 0; i < 4; i++)
#pragma unroll
                for (int j = 0; j < 8; j++) fma2(acc[i][j], a2[i], b2[j]);
        }
    }

    float4 bias0 = *(const float4*)(bias + n0 + c0);
    float4 bias1 = *(const float4*)(bias + n0 + c0 + 4);
    int n = n0 + c0;
    int h = n >> 6, c = n & 63;
#pragma unroll
    for (int i = 0; i < 4; i++) {
#pragma unroll
        for (int half = 0; half < 2; half++) {
            int m = m0 + r0 + 2 * i + half;
            int bb = m >> 11;
            int s  = m & 2047;
            float4 o0, o1;
            if (half == 0) {
                o0.x = lo32(acc[i][0]) + bias0.x; o0.y = lo32(acc[i][1]) + bias0.y;
                o0.z = lo32(acc[i][2]) + bias0.z; o0.w = lo32(acc[i][3]) + bias0.w;
                o1.x = lo32(acc[i][4]) + bias1.x; o1.y = lo32(acc[i][5]) + bias1.y;
                o1.z = lo32(acc[i][6]) + bias1.z; o1.w = lo32(acc[i][7]) + bias1.w;
            } else {
                o0.x = hi32(acc[i][0]) + bias0.x; o0.y = hi32(acc[i][1]) + bias0.y;
                o0.z = hi32(acc[i][2]) + bias0.z; o0.w = hi32(acc[i][3]) + bias0.w;
                o1.x = hi32(acc[i][4]) + bias1.x; o1.y = hi32(acc[i][5]) + bias1.y;
                o1.z = hi32(acc[i][6]) + bias1.z; o1.w = hi32(acc[i][7]) + bias1.w;
            }
            float* po = out + ((size_t)(bb * Hq + h) * Sq + s) * DKq + c;
            *(float4*)po = o0;
            *(float4*)(po + 4) = o1;
        }
    }
}

// ---------------- Kernel A2: v GEMM via 3xTF32 MMA (R14 128x128 version) ----
__global__ __launch_bounds__(256, 2) void v_mma_kernel(const float* __restrict__ bv)
{
    __shared__ __align__(16) float smem[4 * 128 * 20];
    float* Ahs = smem;                 // [128][20] x hi
    float* Als = smem + 2560;          // [128][20] x lo
    float* Bhs = smem + 5120;          // [128][20] Wv hi
    float* Bls = smem + 7680;          // [128][20] Wv lo

    int m0 = blockIdx.y * 128;
    int n0 = blockIdx.x * 128;
    int tid = threadIdx.x;
    int lane = tid & 31, wid = tid >> 5;
    int g = lane >> 2, t4 = lane & 3;
    int wy = wid & 3, wx = wid >> 2;

    float c[2][8][4];
#pragma unroll
    for (int mi = 0; mi < 2; mi++)
#pragma unroll
        for (int ni = 0; ni < 8; ni++)
#pragma unroll
            for (int u = 0; u < 4; u++) c[mi][ni][u] = 0.0f;

    int lrow = tid >> 2, lkq = (tid & 3) * 4;
    const float* pxh0 = g_xh + (size_t)(m0 + lrow)      * 512 + lkq;
    const float* pxh1 = g_xh + (size_t)(m0 + lrow + 64) * 512 + lkq;
    const float* pxl0 = g_xl + (size_t)(m0 + lrow)      * 512 + lkq;
    const float* pxl1 = g_xl + (size_t)(m0 + lrow + 64) * 512 + lkq;
    const float* pwh0 = g_wh + (size_t)(n0 + lrow)      * 512 + lkq;
    const float* pwh1 = g_wh + (size_t)(n0 + lrow + 64) * 512 + lkq;
    const float* pwl0 = g_wl + (size_t)(n0 + lrow)      * 512 + lkq;
    const float* pwl1 = g_wl + (size_t)(n0 + lrow + 64) * 512 + lkq;

    float4 ah0 = *(const float4*)(pxh0);
    float4 ah1 = *(const float4*)(pxh1);
    float4 al0 = *(const float4*)(pxl0);
    float4 al1 = *(const float4*)(pxl1);

    for (int k0 = 0; k0 < 512; k0 += 16) {
        __syncthreads();
        *(float4*)&Ahs[lrow * 20 + lkq]        = ah0;
        *(float4*)&Ahs[(lrow + 64) * 20 + lkq] = ah1;
        *(float4*)&Als[lrow * 20 + lkq]        = al0;
        *(float4*)&Als[(lrow + 64) * 20 + lkq] = al1;
        *(float4*)&Bhs[lrow * 20 + lkq]        = *(const float4*)(pwh0 + k0);
        *(float4*)&Bhs[(lrow + 64) * 20 + lkq] = *(const float4*)(pwh1 + k0);
        *(float4*)&Bls[lrow * 20 + lkq]        = *(const float4*)(pwl0 + k0);
        *(float4*)&Bls[(lrow + 64) * 20 + lkq] = *(const float4*)(pwl1 + k0);
        __syncthreads();
        if (k0 + 16 < 512) {
            ah0 = *(const float4*)(pxh0 + k0 + 16);
            ah1 = *(const float4*)(pxh1 + k0 + 16);
            al0 = *(const float4*)(pxl0 + k0 + 16);
            al1 = *(const float4*)(pxl1 + k0 + 16);
        }
#pragma unroll
        for (int kc = 0; kc < 2; kc++) {
            float afh[2][4], afl[2][4];
#pragma unroll
            for (int mi = 0; mi < 2; mi++) {
                int ao = (wy * 32 + mi * 16 + g) * 20 + kc * 8 + t4;
                afh[mi][0] = Ahs[ao];       afh[mi][1] = Ahs[ao + 160];
                afh[mi][2] = Ahs[ao + 4];   afh[mi][3] = Ahs[ao + 164];
                afl[mi][0] = Als[ao];       afl[mi][1] = Als[ao + 160];
                afl[mi][2] = Als[ao + 4];   afl[mi][3] = Als[ao + 164];
            }
#pragma unroll
            for (int ni = 0; ni < 8; ni++) {
                int bo = (wx * 64 + ni * 8 + g) * 20 + kc * 8 + t4;
                unsigned bh0 = __float_as_uint(Bhs[bo]);
                unsigned bh1 = __float_as_uint(Bhs[bo + 4]);
                unsigned bl0 = __float_as_uint(Bls[bo]);
                unsigned bl1 = __float_as_uint(Bls[bo + 4]);
#pragma unroll
                for (int mi = 0; mi < 2; mi++) {
                    unsigned a0 = __float_as_uint(afh[mi][0]);
                    unsigned a1 = __float_as_uint(afh[mi][1]);
                    unsigned a2 = __float_as_uint(afh[mi][2]);
                    unsigned a3 = __float_as_uint(afh[mi][3]);
                    unsigned l0 = __float_as_uint(afl[mi][0]);
                    unsigned l1 = __float_as_uint(afl[mi][1]);
                    unsigned l2 = __float_as_uint(afl[mi][2]);
                    unsigned l3 = __float_as_uint(afl[mi][3]);
                    MMA_TF32(c[mi][ni], l0, l1, l2, l3, bh0, bh1);  // lo*hi
                    MMA_TF32(c[mi][ni], a0, a1, a2, a3, bl0, bl1);  // hi*lo
                    MMA_TF32(c[mi][ni], a0, a1, a2, a3, bh0, bh1);  // hi*hi
                }
            }
        }
    }

#pragma unroll
    for (int ni = 0; ni < 8; ni++) {
        int n = n0 + wx * 64 + ni * 8 + 2 * t4;
        float2 bi = *(const float2*)(bv + n);
        int h = n >> 6, ci = n & 63;
#pragma unroll
        for (int mi = 0; mi < 2; mi++) {
#pragma unroll
            for (int half = 0; half < 2; half++) {
                int m = m0 + wy * 32 + mi * 16 + g + half * 8;
                int bb = m >> 11, s = m & 2047;
                float2 o;
                o.x = c[mi][ni][half * 2 + 0] + bi.x;
                o.y = c[mi][ni][half * 2 + 1] + bi.y;
                *(float2*)(g_v + ((size_t)(bb * Hq + h) * Sq + s) * DKq + ci) = o;
            }
        }
    }
}

// ---------------- Kernel B: L2-normalize q,k (in place) + tf32 copy ---------
__global__ __launch_bounds__(256) void normalize_split_kernel()
{
    int gw   = blockIdx.x * 8 + (threadIdx.x >> 5);
    int lane = threadIdx.x & 31;
    float* p; float* ph;
    if (gw < BHq * Sq) {
        p  = g_k  + (size_t)gw * 64;
        ph = g_kh + (size_t)gw * 64;
    } else {
        int r = gw - BHq * Sq;
        p  = g_q  + (size_t)r * 64;
        ph = g_qh + (size_t)r * 64;
    }
    float v0 = p[lane], v1 = p[lane + 32];
    float ss = v0 * v0 + v1 * v1;
#pragma unroll
    for (int o = 16; o; o >>= 1) ss += __shfl_xor_sync(0xffffffffu, ss, o);
    float inv = 1.0f / fmaxf(sqrtf(ss), EPSN);
    float x0 = v0 * inv, x1 = v1 * inv;
    p[lane]       = x0;
    p[lane + 32]  = x1;
    ph[lane]      = to_tf32(x0);
    ph[lane + 32] = to_tf32(x1);
}

// ---------------- Kernel C: tf32 mma pruning (top-12) + exact fp32 rescore --
__global__ __launch_bounds__(256, 3) void sim_topk_kernel()
{
    extern __shared__ __align__(16) float sm[];
    float* As = sm;            // [64][68] kn tf32
    float* Bs = sm + 4352;     // [64][68] qn tf32
    float* Ss = sm + 8704;     // [64][68] sim tile; later kn fp32 tile

    int bh = blockIdx.y;
    int i0 = blockIdx.x * 64;
    int tid = threadIdx.x;
    int lane = tid & 31;
    int wid = tid >> 5;
    int g = lane >> 2, t4 = lane & 3;
    int wr = (wid & 3) * 16;
    int jbase = (wid >> 2) * 32;

    const float* khb = g_kh + (size_t)bh * Sq * DKq;
    const float* qhb = g_qh + (size_t)bh * Sq * DKq;

#pragma unroll
    for (int p = 0; p < 4; p++) {
        int f = tid + 256 * p;
        int r = f >> 4, dq = (f & 15) * 4;
        *(float4*)&As[r * 68 + dq] = *(const float4*)(khb + (size_t)(i0 + r) * 64 + dq);
    }

    float tv[NC]; int ti[NC];
#pragma unroll
    for (int q = 0; q < NC; q++) { tv[q] = -1.0f; ti[q] = 0; }

    int row = tid >> 2, part = tid & 3;

    const unsigned* Ah = (const unsigned*)As;
    const unsigned* Bh = (const unsigned*)Bs;

    for (int j0 = 0; j0 < Sq; j0 += 64) {
        __syncthreads();
#pragma unroll
        for (int p = 0; p < 4; p++) {
            int f = tid + 256 * p;
            int r = f >> 4, dq = (f & 15) * 4;
            *(float4*)&Bs[r * 68 + dq] =
                *(const float4*)(qhb + (size_t)(j0 + r) * 64 + dq);
        }
        __syncthreads();

        float c[4][4];
#pragma unroll
        for (int jc = 0; jc < 4; jc++)
#pragma unroll
            for (int u = 0; u < 4; u++) c[jc][u] = 0.0f;

#pragma unroll
        for (int kc = 0; kc < 8; kc++) {
            int ao = (wr + g) * 68 + kc * 8 + t4;
            unsigned ah0 = Ah[ao], ah1 = Ah[ao + 544], ah2 = Ah[ao + 4], ah3 = Ah[ao + 548];
#pragma unroll
            for (int jc = 0; jc < 4; jc++) {
                int bo = (jbase + jc * 8 + g) * 68 + kc * 8 + t4;
                unsigned bh0 = Bh[bo], bh1 = Bh[bo + 4];
                MMA_TF32(c[jc], ah0, ah1, ah2, ah3, bh0, bh1);
            }
        }

#pragma unroll
        for (int jc = 0; jc < 4; jc++) {
            int col = jbase + jc * 8 + 2 * t4;
            int rr  = wr + g;
            float2 s0, s1;
            s0.x = fmaxf(c[jc][0], 0.0f); s0.y = fmaxf(c[jc][1], 0.0f);
            s1.x = fmaxf(c[jc][2], 0.0f); s1.y = fmaxf(c[jc][3], 0.0f);
            *(float2*)&Ss[rr * 68 + col]       = s0;
            *(float2*)&Ss[(rr + 8) * 68 + col] = s1;
        }
        __syncthreads();

#pragma unroll
        for (int t = 0; t < 4; t++) {
            float4 v4 = *(const float4*)&Ss[row * 68 + part * 16 + t * 4];
            int cb = j0 + part * 16 + t * 4;
            float vv[4] = {v4.x, v4.y, v4.z, v4.w};
#pragma unroll
            for (int u = 0; u < 4; u++) {
                float v = vv[u];
                if (v > tv[NC - 1]) {
                    tv[NC - 1] = v; ti[NC - 1] = cb + u;
#pragma unroll
                    for (int q = NC - 1; q > 0; q--) {
                        if (tv[q] > tv[q - 1]) {
                            float tf = tv[q]; tv[q] = tv[q - 1]; tv[q - 1] = tf;
                            int tt = ti[q]; ti[q] = ti[q - 1]; ti[q - 1] = tt;
                        }
                    }
                }
            }
        }
    }
    __syncthreads();

    float* Mv = sm;
    int*   Mi = (int*)(sm + 3072);
    int*   Ci = (int*)(sm + 6144);
    float* Cv = sm + 6912;
#pragma unroll
    for (int q = 0; q < NC; q++) {
        Mv[tid * NC + q] = tv[q];
        Mi[tid * NC + q] = ti[q];
    }
#pragma unroll
    for (int p = 0; p < 4; p++) {
        int f = tid + 256 * p;
        int r = f >> 4, dq = (f & 15) * 4;
        *(float4*)&Ss[r * 68 + dq] =
            *(const float4*)(g_k + ((size_t)bh * Sq + i0 + r) * 64 + dq);
    }
    __syncthreads();

    if (tid < 64) {
        int pos0 = 0, pos1 = 0, pos2 = 0, pos3 = 0;
        for (int kk = 0; kk < NC; kk++) {
            float bv = -2.0f; int bi = 0x7fffffff, bp = 0;
            {
                float v = Mv[(tid * 4 + 0) * NC + pos0]; int ix = Mi[(tid * 4 + 0) * NC + pos0];
                if (v > bv || (v == bv && ix < bi)) { bv = v; bi = ix; bp = 0; }
            }
            {
                float v = Mv[(tid * 4 + 1) * NC + pos1]; int ix = Mi[(tid * 4 + 1) * NC + pos1];
                if (v > bv || (v == bv && ix < bi)) { bv = v; bi = ix; bp = 1; }
            }
            {
                float v = Mv[(tid * 4 + 2) * NC + pos2]; int ix = Mi[(tid * 4 + 2) * NC + pos2];
                if (v > bv || (v == bv && ix < bi)) { bv = v; bi = ix; bp = 2; }
            }
            {
                float v = Mv[(tid * 4 + 3) * NC + pos3]; int ix = Mi[(tid * 4 + 3) * NC + pos3];
                if (v > bv || (v == bv && ix < bi)) { bv = v; bi = ix; bp = 3; }
            }
            Ci[tid * NC + kk] = bi;
            if (bp == 0) pos0++; else if (bp == 1) pos1++; else if (bp == 2) pos2++; else pos3++;
        }
    }
    __syncthreads();

    {
        int r = tid >> 2, p = tid & 3;
        const float* kr = &Ss[r * 68];
#pragma unroll
        for (int s2 = 0; s2 < 3; s2++) {
            int c2 = p + 4 * s2;
            int j = Ci[r * NC + c2];
            const float* qrow = g_q + ((size_t)bh * Sq + j) * 64;
            float s = 0.0f;
#pragma unroll
            for (int d = 0; d < 64; d += 4) {
                float4 qv = *(const float4*)(qrow + d);
                s = fmaf(kr[d + 0], qv.x, s);
                s = fmaf(kr[d + 1], qv.y, s);
                s = fmaf(kr[d + 2], qv.z, s);
                s = fmaf(kr[d + 3], qv.w, s);
            }
            Cv[r * NC + c2] = fmaxf(s, 0.0f);
        }
    }
    __syncthreads();

    if (tid < 64) {
        float vals[NC]; int cand[NC];
#pragma unroll
        for (int c2 = 0; c2 < NC; c2++) {
            vals[c2] = Cv[tid * NC + c2];
            cand[c2] = Ci[tid * NC + c2];
        }
        int obase = (bh * Sq + i0 + tid) * KN;
        for (int a = 0; a < KN; a++) {
            int best = a;
            for (int c2 = a + 1; c2 < NC; c2++) {
                if (vals[c2] > vals[best] ||
                    (vals[c2] == vals[best] && cand[c2] < cand[best]))
                    best = c2;
            }
            float tvv = vals[a]; vals[a] = vals[best]; vals[best] = tvv;
            int   tii = cand[a]; cand[a] = cand[best]; cand[best] = tii;
            g_idx[obase + a] = cand[a];
        }
    }
}

// ---------------- prep: transpose conv_w [o][c][kk] -> Wt[kk][c][o] ---------
__global__ void transpose_convw_kernel(const float* __restrict__ w)
{
    int t = blockIdx.x * 256 + threadIdx.x;
    if (t < KN * DKq * DKq) {
        int o = t & 63, c = (t >> 6) & 63, kk = t >> 12;
        g_wt[t] = w[(o * 64 + c) * KN + kk];
    }
}

// ---------------- Kernel D: gather + conv; epilogue writes y^T hi/lo split --
__global__ __launch_bounds__(128, 2) void conv_kernel(const float* __restrict__ convb)
{
    extern __shared__ float smd[];
    float* v_s  = smd;                   // [288][64]
    float* w_s  = smd + 288 * 64;        // [64 c][64 o]
    int*   sidx = (int*)(smd + 288 * 64 + 4096);  // [288]

    int bh = blockIdx.y;
    int i0 = blockIdx.x * 32;
    int b  = bh >> 3, h = bh & 7;
    int tid = threadIdx.x;

    for (int t = tid; t < 288; t += 128)
        sidx[t] = g_idx[(bh * Sq + i0 + t / KN) * KN + (t % KN)];

    float4 wreg[8];
#pragma unroll
    for (int p = 0; p < 8; p++)
        wreg[p] = *(const float4*)(g_wt + (tid + 128 * p) * 4);

    __syncthreads();

    const float* vbase = g_v + (size_t)bh * Sq * DKq;
    for (int p = 0; p < 36; p++) {
        int f = tid + 128 * p;
        int r = f >> 4, fq = (f & 15) * 4;
        int j = sidx[r];
        float4 vv = *(const float4*)(vbase + (size_t)j * 64 + fq);
        *(float4*)&v_s[r * 64 + fq] = vv;
    }

    int og = tid & 15; int o0 = og * 4;
    int ig = tid >> 4;
    ull acc[4][2];
#pragma unroll
    for (int t = 0; t < 4; t++) { acc[t][0] = 0ULL; acc[t][1] = 0ULL; }

    for (int kk = 0; kk < KN; kk++) {
        __syncthreads();
#pragma unroll
        for (int p = 0; p < 8; p++)
            *(float4*)&w_s[(tid + 128 * p) * 4] = wreg[p];
        __syncthreads();
        if (kk + 1 < KN) {
#pragma unroll
            for (int p = 0; p < 8; p++)
                wreg[p] = *(const float4*)(g_wt + (kk + 1) * 4096 + (tid + 128 * p) * 4);
        }
#pragma unroll 4
        for (int c = 0; c < 64; c++) {
            ulonglong2 wp = *(const ulonglong2*)&w_s[c * 64 + o0];
#pragma unroll
            for (int t = 0; t < 4; t++) {
                ull v2 = pack2(v_s[(((ig * 4 + t) * KN) + kk) * 64 + c]);
                fma2(acc[t][0], v2, wp.x);
                fma2(acc[t][1], v2, wp.y);
            }
        }
    }

    float4 cb = *(const float4*)(convb + o0);
    int colbase = (h * 64 + (i0 >> 5)) * Mq + b * Sq;
#pragma unroll
    for (int t = 0; t < 4; t++) {
        int il = ig * 4 + t;
        int sp = ((i0 + il) & 31) * 64 + o0;
        float o[4];
        o[0] = lo32(acc[t][0]) + cb.x;
        o[1] = hi32(acc[t][0]) + cb.y;
        o[2] = lo32(acc[t][1]) + cb.z;
        o[3] = hi32(acc[t][1]) + cb.w;
        float4 hh, ll;
        hh.x = to_tf32(o[0]); ll.x = to_tf32(o[0] - hh.x);
        hh.y = to_tf32(o[1]); ll.y = to_tf32(o[1] - hh.y);
        hh.z = to_tf32(o[2]); ll.z = to_tf32(o[2] - hh.z);
        hh.w = to_tf32(o[3]); ll.w = to_tf32(o[3] - hh.w);
        *(float4*)&g_xh[colbase + sp] = hh;
        *(float4*)&g_xl[colbase + sp] = ll;
    }
}

// ---------------- Kernel E: out GEMM via 3xTF32 MMA (R14 128x128 version) ---
__global__ __launch_bounds__(256, 2) void out_mma_kernel(
    const float* __restrict__ bo, float* __restrict__ outp)
{
    __shared__ __align__(16) float Ahs[16 * 132];
    __shared__ __align__(16) float Als[16 * 132];
    __shared__ __align__(16) float Bhs[128 * 20];
    __shared__ __align__(16) float Bls[128 * 20];

    int m0 = blockIdx.y * 128, n0 = blockIdx.x * 128;
    int tid = threadIdx.x;
    int lane = tid & 31, wid = tid >> 5;
    int g = lane >> 2, t4 = lane & 3;
    int wy = wid & 3, wx = wid >> 2;

    float c[2][8][4];
#pragma unroll
    for (int mi = 0; mi < 2; mi++)
#pragma unroll
        for (int ni = 0; ni < 8; ni++)
#pragma unroll
            for (int u = 0; u < 4; u++) c[mi][ni][u] = 0.0f;

    int fk = tid >> 5, fm = tid & 31;            // A fill: rows fk, fk+8
    int lrow = tid >> 2, lkq = (tid & 3) * 4;    // B fill

    const float* pah0 = g_xh + (size_t)fk * Mq + m0 + fm * 4;        // y hi
    const float* pah1 = g_xh + (size_t)(fk + 8) * Mq + m0 + fm * 4;
    const float* pal0 = g_xl + (size_t)fk * Mq + m0 + fm * 4;        // y lo
    const float* pal1 = g_xl + (size_t)(fk + 8) * Mq + m0 + fm * 4;
    const float* pbh0 = g_wh + 262144 + (size_t)(n0 + lrow)      * 512 + lkq;  // Wo hi
    const float* pbh1 = g_wh + 262144 + (size_t)(n0 + lrow + 64) * 512 + lkq;
    const float* pbl0 = g_wl + 262144 + (size_t)(n0 + lrow)      * 512 + lkq;  // Wo lo
    const float* pbl1 = g_wl + 262144 + (size_t)(n0 + lrow + 64) * 512 + lkq;

    float4 ah0 = *(const float4*)(pah0);
    float4 ah1 = *(const float4*)(pah1);
    float4 al0 = *(const float4*)(pal0);
    float4 al1 = *(const float4*)(pal1);

    for (int k0 = 0; k0 < 512; k0 += 16) {
        __syncthreads();
        *(float4*)&Ahs[fk * 132 + fm * 4]       = ah0;
        *(float4*)&Ahs[(fk + 8) * 132 + fm * 4] = ah1;
        *(float4*)&Als[fk * 132 + fm * 4]       = al0;
        *(float4*)&Als[(fk + 8) * 132 + fm * 4] = al1;
        *(float4*)&Bhs[lrow * 20 + lkq]         = *(const float4*)(pbh0 + k0);
        *(float4*)&Bhs[(lrow + 64) * 20 + lkq]  = *(const float4*)(pbh1 + k0);
        *(float4*)&Bls[lrow * 20 + lkq]         = *(const float4*)(pbl0 + k0);
        *(float4*)&Bls[(lrow + 64) * 20 + lkq]  = *(const float4*)(pbl1 + k0);
        __syncthreads();
        if (k0 + 16 < 512) {
            ah0 = *(const float4*)(pah0 + (size_t)(k0 + 16) * Mq);
            ah1 = *(const float4*)(pah1 + (size_t)(k0 + 16) * Mq);
            al0 = *(const float4*)(pal0 + (size_t)(k0 + 16) * Mq);
            al1 = *(const float4*)(pal1 + (size_t)(k0 + 16) * Mq);
        }
#pragma unroll
        for (int kc = 0; kc < 2; kc++) {
            float afh[2][4], afl[2][4];
#pragma unroll
            for (int mi = 0; mi < 2; mi++) {
                int mloc = wy * 32 + mi * 16 + g;
                int ao = (kc * 8 + t4) * 132 + mloc;
                afh[mi][0] = Ahs[ao];             afh[mi][1] = Ahs[ao + 8];
                afh[mi][2] = Ahs[ao + 4 * 132];   afh[mi][3] = Ahs[ao + 4 * 132 + 8];
                afl[mi][0] = Als[ao];             afl[mi][1] = Als[ao + 8];
                afl[mi][2] = Als[ao + 4 * 132];   afl[mi][3] = Als[ao + 4 * 132 + 8];
            }
#pragma unroll
            for (int ni = 0; ni < 8; ni++) {
                int bo_ = (wx * 64 + ni * 8 + g) * 20 + kc * 8 + t4;
                unsigned bh0 = __float_as_uint(Bhs[bo_]);
                unsigned bh1 = __float_as_uint(Bhs[bo_ + 4]);
                unsigned bl0 = __float_as_uint(Bls[bo_]);
                unsigned bl1 = __float_as_uint(Bls[bo_ + 4]);
#pragma unroll
                for (int mi = 0; mi < 2; mi++) {
                    unsigned a0 = __float_as_uint(afh[mi][0]);
                    unsigned a1 = __float_as_uint(afh[mi][1]);
                    unsigned a2 = __float_as_uint(afh[mi][2]);
                    unsigned a3 = __float_as_uint(afh[mi][3]);
                    unsigned l0 = __float_as_uint(afl[mi][0]);
                    unsigned l1 = __float_as_uint(afl[mi][1]);
                    unsigned l2 = __float_as_uint(afl[mi][2]);
                    unsigned l3 = __float_as_uint(afl[mi][3]);
                    MMA_TF32(c[mi][ni], l0, l1, l2, l3, bh0, bh1);  // lo*hi
                    MMA_TF32(c[mi][ni], a0, a1, a2, a3, bl0, bl1);  // hi*lo
                    MMA_TF32(c[mi][ni], a0, a1, a2, a3, bh0, bh1);  // hi*hi
                }
            }
        }
    }

#pragma unroll
    for (int ni = 0; ni < 8; ni++) {
        int n = n0 + wx * 64 + ni * 8 + 2 * t4;
        float2 bi = *(const float2*)(bo + n);
#pragma unroll
        for (int mi = 0; mi < 2; mi++) {
#pragma unroll
            for (int half = 0; half < 2; half++) {
                int m = m0 + wy * 32 + mi * 16 + g + half * 8;
                float2 o;
                o.x = c[mi][ni][half * 2 + 0] + bi.x;
                o.y = c[mi][ni][half * 2 + 1] + bi.y;
                *(float2*)(outp + (size_t)m * 512 + n) = o;
            }
        }
    }
}

// ---------------- launch -----------------------------------------------------
extern "C" void kernel_launch(void* const* d_in, const int* in_sizes, int n_in,
                              void* d_out, int out_size)
{
    (void)in_sizes; (void)n_in; (void)out_size;
    const float* x      = (const float*)d_in[0];
    const float* Wq_w   = (const float*)d_in[1];
    const float* Wq_b   = (const float*)d_in[2];
    const float* Wk_w   = (const float*)d_in[3];
    const float* Wk_b   = (const float*)d_in[4];
    const float* Wv_w   = (const float*)d_in[5];
    const float* Wv_b   = (const float*)d_in[6];
    const float* Wo_w   = (const float*)d_in[7];
    const float* Wo_b   = (const float*)d_in[8];
    const float* conv_w = (const float*)d_in[9];
    const float* conv_b = (const float*)d_in[10];
    float* outp = (float*)d_out;

    const int SMEM_C = 13056 * 4;                            // 52224 B
    const int SMEM_D = (288 * 64 + 64 * 64) * 4 + 288 * 4;   // 91264 B
    cudaFuncSetAttribute(sim_topk_kernel, cudaFuncAttributeMaxDynamicSharedMemorySize, SMEM_C);
    cudaFuncSetAttribute(conv_kernel,     cudaFuncAttributeMaxDynamicSharedMemorySize, SMEM_D);

    split_x_kernel<<<4096, 256>>>(x);                     // 1M float4
    split_w2_kernel<<<512, 256>>>(Wv_w, Wo_w);            // 131072 float4
    qk_gemm_kernel<<<dim3(4, 64, 2), 256>>>(x, Wq_w, Wq_b, Wk_w, Wk_b);
    v_mma_kernel<<<dim3(4, 64), 256>>>(Wv_b);
    normalize_split_kernel<<<16384, 256>>>();
    transpose_convw_kernel<<<144, 256>>>(conv_w);
    sim_topk_kernel<<<dim3(32, 32), 256, SMEM_C>>>();
    conv_kernel<<<dim3(64, 32), 128, SMEM_D>>>(conv_b);
    out_mma_kernel<<<dim3(4, 64), 256>>>(Wo_b, outp);
}